// round 9
// baseline (speedup 1.0000x reference)
#include <cuda_runtime.h>

#define NB    32
#define C_IN  64
#define HH    64
#define WWW   64
#define C_OUT 128
#define CONN  4

#define BAND  8                      // output rows per block
#define RS    (BAND + 2)             // staged rows (band +/- 1, edge-clamped)
#define SROW  64                     // floats per staged row
#define SCH   (RS * SROW)            // 640 floats per channel slab
#define SMEM_FLOATS (C_IN * SCH)     // 40960 floats
#define SMEM_BYTES  (SMEM_FLOATS * 4)  // 163840 B

// Decoded connection descriptors: {c*SCH (smem channel offset), di*64, dj, w_bits}
__device__ int4 g_desc[C_OUT * CONN];

__global__ void prep_kernel(const float* __restrict__ w, const int* __restrict__ conn)
{
    const int t = threadIdx.x + blockIdx.x * blockDim.x;   // 0..511
    if (t >= C_OUT * CONN) return;
    const int idx = conn[t];
    const int c   = idx / 9;
    const int rem = idx - c * 9;
    const int di  = rem / 3;
    const int dj  = rem - di * 3;
    int4 d;
    d.x = c * SCH;          // smem channel-slab base (floats)
    d.y = di * SROW;        // staged-row offset: local row = t + di  (in [0, RS-1])
    d.z = dj;
    d.w = __float_as_int(w[t]);
    g_desc[t] = d;
}

__global__ __launch_bounds__(1024) void lp_main(
    const float* __restrict__ x,      // (32,64,64,64)
    const float* __restrict__ bias,   // (128)
    float*       __restrict__ out)    // (32,128,64,64)
{
    extern __shared__ float sx[];     // [C_IN][RS][SROW]

    const int tid  = threadIdx.x;
    const int band = blockIdx.x;
    const int b    = blockIdx.y;
    const int ho0  = band * BAND;

    // ---- stage: rows [ho0-1 .. ho0+BAND] of all 64 channels (edge-clamped) ----
    const float* __restrict__ xb = x + (long long)b * (C_IN * HH * WWW);
    #pragma unroll
    for (int i = tid; i < SMEM_FLOATS / 4; i += 1024) {   // 10 iters, float4 each
        const int w4 = i & 15;
        const int k  = (i >> 4) % RS;
        const int ch = i / (RS * 16);
        const int r  = min(max(ho0 - 1 + k, 0), HH - 1);
        const float4 v = __ldg(reinterpret_cast<const float4*>(
            xb + (ch * HH + r) * WWW + w4 * 4));
        *reinterpret_cast<float4*>(&sx[ch * SCH + k * SROW + w4 * 4]) = v;
    }
    __syncthreads();

    // ---- compute: loop over co; thread = (co-group, band-row, wo-quad) ----
    const int quad = tid & 15;           // 0..15
    const int wo0  = quad * 4;
    const int t    = (tid >> 4) & 7;     // row within band
    const int cg   = tid >> 7;           // 0..7 : co offset group (uniform per warp)
    const int ho   = ho0 + t;
    const int trow = t * SROW;

    float* __restrict__ outb =
        out + (long long)b * (C_OUT * HH * WWW) + ho * WWW + wo0;

    #pragma unroll 4
    for (int it = 0; it < C_OUT / 8; ++it) {
        const int co = it * 8 + cg;

        float a0 = 0.f, a1 = 0.f, a2 = 0.f, a3 = 0.f;   // |.| >= 0: safe identity

        #pragma unroll
        for (int j = 0; j < CONN; ++j) {
            const int4  d  = __ldg(&g_desc[co * CONN + j]);
            const float wj = __int_as_float(d.w);
            const int   ro = d.x + d.y + trow;           // staged row base (floats)

            const float4 v = *reinterpret_cast<const float4*>(&sx[ro + wo0]);

            float e0, e1, e2, e3;
            if (d.z == 1) {                              // uniform per warp
                e0 = v.x; e1 = v.y; e2 = v.z; e3 = v.w;
            } else if (d.z == 0) {
                const float left = sx[ro + max(wo0 - 1, 0)];   // clamp wo=-1 -> 0
                e0 = left; e1 = v.x; e2 = v.y; e3 = v.z;
            } else {                                     // d.z == 2
                const float right = sx[ro + min(wo0 + 4, WWW - 1)]; // clamp 64 -> 63
                e0 = v.y; e1 = v.z; e2 = v.w; e3 = right;
            }

            a0 = fmaxf(a0, fabsf(wj - e0));
            a1 = fmaxf(a1, fabsf(wj - e1));
            a2 = fmaxf(a2, fabsf(wj - e2));
            a3 = fmaxf(a3, fabsf(wj - e3));
        }

        const float bs = __ldg(&bias[co]);
        float4 r;
        r.x = a0 + bs; r.y = a1 + bs; r.z = a2 + bs; r.w = a3 + bs;
        *reinterpret_cast<float4*>(&outb[co * (HH * WWW)]) = r;
    }
}

extern "C" void kernel_launch(void* const* d_in, const int* in_sizes, int n_in,
                              void* d_out, int out_size)
{
    const float* x    = (const float*)d_in[0];
    const float* w    = (const float*)d_in[1];
    const float* bias = (const float*)d_in[2];
    const int*   conn = (const int*)  d_in[3];
    float*       out  = (float*)d_out;

    prep_kernel<<<2, 256>>>(w, conn);

    cudaFuncSetAttribute(lp_main, cudaFuncAttributeMaxDynamicSharedMemorySize,
                         SMEM_BYTES);
    dim3 grid(HH / BAND, NB);            // (8, 32) = 256 blocks
    lp_main<<<grid, 1024, SMEM_BYTES>>>(x, bias, out);
}

// round 13
// speedup vs baseline: 2.0208x; 2.0208x over previous
#include <cuda_runtime.h>

#define NB    32
#define C_IN  64
#define HH    64
#define WWW   64
#define C_OUT 128
#define CONN  4

// Decoded connection descriptors: {c*HH*WWW, di-1, dj, w_bits}
__device__   int4  g_desc[C_OUT * CONN];
__constant__ int4  c_desc[C_OUT * CONN];
__constant__ float c_bias[C_OUT];

__global__ void prep_kernel(const float* __restrict__ w, const int* __restrict__ conn)
{
    const int t = threadIdx.x + blockIdx.x * blockDim.x;   // 0..511
    if (t >= C_OUT * CONN) return;
    const int idx = conn[t];
    const int c   = idx / 9;
    const int rem = idx - c * 9;
    const int di  = rem / 3;
    const int dj  = rem - di * 3;
    int4 d;
    d.x = c * HH * WWW;
    d.y = di - 1;
    d.z = dj;
    d.w = __float_as_int(w[t]);
    g_desc[t] = d;
}

__global__ __launch_bounds__(256, 5) void lp_main(
    const float* __restrict__ x,      // (32,64,64,64)
    float*       __restrict__ out)    // (32,128,64,64)
{
    const int qx   = threadIdx.x;                    // 0..15 -> wo quad
    const int hoA  = blockIdx.x * 32 + threadIdx.y;  // [0..15] u [32..47]
    const int hoB  = hoA + 16;                       // [16..31] u [48..63]
    const int b    = blockIdx.y;
    const int co   = blockIdx.z;
    const int wo0  = qx * 4;

    const float* __restrict__ xb = x + b * (C_IN * HH * WWW) + wo0;
    const bool pL = (qx == 0);
    const bool pR = (qx == 15);

    float aA0 = 0.f, aA1 = 0.f, aA2 = 0.f, aA3 = 0.f;  // |.| >= 0: safe identity
    float aB0 = 0.f, aB1 = 0.f, aB2 = 0.f, aB3 = 0.f;

    // hoA + d.y in [-1, 48] -> only lower clamp needed.
    // hoB + d.y in [15, 64] -> only upper clamp needed.
#define GATHER(d, vA, vB)                                                      \
    float4 vA, vB;                                                             \
    {                                                                          \
        const int shA = max(hoA + d.y, 0);                                     \
        const int shB = min(hoB + d.y, HH - 1);                                \
        vA = __ldg(reinterpret_cast<const float4*>(xb + d.x + shA * WWW));     \
        vB = __ldg(reinterpret_cast<const float4*>(xb + d.x + shB * WWW));     \
    }

#define PROCESS(d, va, vb)                                                     \
    {                                                                          \
        const float wj = __int_as_float(d.w);                                  \
        float eA0, eA1, eA2, eA3, eB0, eB1, eB2, eB3;                          \
        if (d.z == 1) {                                                        \
            eA0 = va.x; eA1 = va.y; eA2 = va.z; eA3 = va.w;                    \
            eB0 = vb.x; eB1 = vb.y; eB2 = vb.z; eB3 = vb.w;                    \
        } else if (d.z == 0) {                                                 \
            float lA = __shfl_up_sync(0xffffffffu, va.w, 1, 16);               \
            float lB = __shfl_up_sync(0xffffffffu, vb.w, 1, 16);               \
            if (pL) { lA = va.x; lB = vb.x; }  /* clamp wo=-1 -> wo=0 */       \
            eA0 = lA;  eA1 = va.x; eA2 = va.y; eA3 = va.z;                     \
            eB0 = lB;  eB1 = vb.x; eB2 = vb.y; eB3 = vb.z;                     \
        } else {                                                               \
            float rA = __shfl_down_sync(0xffffffffu, va.x, 1, 16);             \
            float rB = __shfl_down_sync(0xffffffffu, vb.x, 1, 16);             \
            if (pR) { rA = va.w; rB = vb.w; }  /* clamp wo=64 -> wo=63 */      \
            eA0 = va.y; eA1 = va.z; eA2 = va.w; eA3 = rA;                      \
            eB0 = vb.y; eB1 = vb.z; eB2 = vb.w; eB3 = rB;                      \
        }                                                                      \
        aA0 = fmaxf(aA0, fabsf(wj - eA0));                                     \
        aA1 = fmaxf(aA1, fabsf(wj - eA1));                                     \
        aA2 = fmaxf(aA2, fabsf(wj - eA2));                                     \
        aA3 = fmaxf(aA3, fabsf(wj - eA3));                                     \
        aB0 = fmaxf(aB0, fabsf(wj - eB0));                                     \
        aB1 = fmaxf(aB1, fabsf(wj - eB1));                                     \
        aB2 = fmaxf(aB2, fabsf(wj - eB2));                                     \
        aB3 = fmaxf(aB3, fabsf(wj - eB3));                                     \
    }

    {   // conn pair 0,1
        const int4 d0 = c_desc[co * CONN + 0];
        const int4 d1 = c_desc[co * CONN + 1];
        GATHER(d0, vA0, vB0)
        GATHER(d1, vA1, vB1)
        PROCESS(d0, vA0, vB0)
        PROCESS(d1, vA1, vB1)
    }
    {   // conn pair 2,3
        const int4 d2 = c_desc[co * CONN + 2];
        const int4 d3 = c_desc[co * CONN + 3];
        GATHER(d2, vA2, vB2)
        GATHER(d3, vA3, vB3)
        PROCESS(d2, vA2, vB2)
        PROCESS(d3, vA3, vB3)
    }
#undef GATHER
#undef PROCESS

    const float bs = c_bias[co];
    const int ob = ((b * C_OUT + co) * HH + hoA) * WWW + wo0;   // < 2^25: 32-bit ok
    float4 rA, rB;
    rA.x = aA0 + bs; rA.y = aA1 + bs; rA.z = aA2 + bs; rA.w = aA3 + bs;
    rB.x = aB0 + bs; rB.y = aB1 + bs; rB.z = aB2 + bs; rB.w = aB3 + bs;
    *reinterpret_cast<float4*>(out + ob)             = rA;
    *reinterpret_cast<float4*>(out + ob + 16 * WWW)  = rB;
}

extern "C" void kernel_launch(void* const* d_in, const int* in_sizes, int n_in,
                              void* d_out, int out_size)
{
    const float* x    = (const float*)d_in[0];
    const float* w    = (const float*)d_in[1];
    const float* bias = (const float*)d_in[2];
    const int*   conn = (const int*)  d_in[3];
    float*       out  = (float*)d_out;

    prep_kernel<<<2, 256>>>(w, conn);

    // D2D copies into constant bank (graph-capturable memcpy nodes)
    void* gdesc_ptr = nullptr;
    cudaGetSymbolAddress(&gdesc_ptr, g_desc);
    cudaMemcpyToSymbolAsync(c_desc, gdesc_ptr, sizeof(int4) * C_OUT * CONN, 0,
                            cudaMemcpyDeviceToDevice);
    cudaMemcpyToSymbolAsync(c_bias, bias, sizeof(float) * C_OUT, 0,
                            cudaMemcpyDeviceToDevice);

    dim3 block(16, 16);                  // half-warp = contiguous 64-wo row
    dim3 grid(HH / 32, NB, C_OUT);       // (2, 32, 128); each thread: 2 rows
    lp_main<<<grid, block>>>(x, out);
}

// round 15
// speedup vs baseline: 2.1600x; 1.0689x over previous
#include <cuda_runtime.h>

#define NB    32
#define C_IN  64
#define HH    64
#define WWW   64
#define C_OUT 128
#define CONN  4

// Decoded connection descriptors: {c*HH*WWW, (di-1)*WWW, dj, w_bits}
__device__ int4 g_desc[C_OUT * CONN];

__global__ void prep_kernel(const float* __restrict__ w, const int* __restrict__ conn)
{
    const int t = threadIdx.x + blockIdx.x * blockDim.x;   // 0..511
    if (t >= C_OUT * CONN) return;
    const int idx = conn[t];
    const int c   = idx / 9;
    const int rem = idx - c * 9;
    const int di  = rem / 3;
    const int dj  = rem - di * 3;
    int4 d;
    d.x = c * HH * WWW;
    d.y = (di - 1) * WWW;       // pre-scaled row offset
    d.z = dj;
    d.w = __float_as_int(w[t]);
    g_desc[t] = d;
}

__global__ __launch_bounds__(256, 6) void lp_main(
    const float* __restrict__ x,      // (32,64,64,64)
    const float* __restrict__ bias,   // (128)
    float*       __restrict__ out)    // (32,128,64,64)
{
    const int qx   = threadIdx.x;                    // 0..15 -> wo quad
    const int hoA  = blockIdx.x * 32 + threadIdx.y;  // [0..15] u [32..47]
    const int b    = blockIdx.y;
    const int co   = blockIdx.z;
    const int wo0  = qx * 4;

    const int hoAW = hoA * WWW;                      // scaled row bases
    const int hoBW = hoAW + 16 * WWW;

    const float* __restrict__ xb = x + b * (C_IN * HH * WWW) + wo0;
    const bool pL = (qx == 0);
    const bool pR = (qx == 15);

    float aA0 = 0.f, aA1 = 0.f, aA2 = 0.f, aA3 = 0.f;  // |.| >= 0: safe identity
    float aB0 = 0.f, aB1 = 0.f, aB2 = 0.f, aB3 = 0.f;

    // hoAW + d.y in [-64, 48*64] -> only lower clamp needed.
    // hoBW + d.y in [15*64, 64*64] -> only upper clamp needed.
#define GATHER(d, vA, vB)                                                      \
    float4 vA, vB;                                                             \
    {                                                                          \
        const int rA_ = max(hoAW + d.y, 0);                                    \
        const int rB_ = min(hoBW + d.y, (HH - 1) * WWW);                       \
        vA = __ldg(reinterpret_cast<const float4*>(xb + d.x + rA_));           \
        vB = __ldg(reinterpret_cast<const float4*>(xb + d.x + rB_));           \
    }

#define PROCESS(d, va, vb)                                                     \
    {                                                                          \
        const float wj = __int_as_float(d.w);                                  \
        float eA0, eA1, eA2, eA3, eB0, eB1, eB2, eB3;                          \
        if (d.z == 1) {                                                        \
            eA0 = va.x; eA1 = va.y; eA2 = va.z; eA3 = va.w;                    \
            eB0 = vb.x; eB1 = vb.y; eB2 = vb.z; eB3 = vb.w;                    \
        } else if (d.z == 0) {                                                 \
            float lA = __shfl_up_sync(0xffffffffu, va.w, 1, 16);               \
            float lB = __shfl_up_sync(0xffffffffu, vb.w, 1, 16);               \
            if (pL) { lA = va.x; lB = vb.x; }  /* clamp wo=-1 -> wo=0 */       \
            eA0 = lA;  eA1 = va.x; eA2 = va.y; eA3 = va.z;                     \
            eB0 = lB;  eB1 = vb.x; eB2 = vb.y; eB3 = vb.z;                     \
        } else {                                                               \
            float rA = __shfl_down_sync(0xffffffffu, va.x, 1, 16);             \
            float rB = __shfl_down_sync(0xffffffffu, vb.x, 1, 16);             \
            if (pR) { rA = va.w; rB = vb.w; }  /* clamp wo=64 -> wo=63 */      \
            eA0 = va.y; eA1 = va.z; eA2 = va.w; eA3 = rA;                      \
            eB0 = vb.y; eB1 = vb.z; eB2 = vb.w; eB3 = rB;                      \
        }                                                                      \
        aA0 = fmaxf(aA0, fabsf(wj - eA0));                                     \
        aA1 = fmaxf(aA1, fabsf(wj - eA1));                                     \
        aA2 = fmaxf(aA2, fabsf(wj - eA2));                                     \
        aA3 = fmaxf(aA3, fabsf(wj - eA3));                                     \
        aB0 = fmaxf(aB0, fabsf(wj - eB0));                                     \
        aB1 = fmaxf(aB1, fabsf(wj - eB1));                                     \
        aB2 = fmaxf(aB2, fabsf(wj - eB2));                                     \
        aB3 = fmaxf(aB3, fabsf(wj - eB3));                                     \
    }

    {   // conn pair 0,1
        const int4 d0 = __ldg(&g_desc[co * CONN + 0]);
        const int4 d1 = __ldg(&g_desc[co * CONN + 1]);
        GATHER(d0, vA0, vB0)
        GATHER(d1, vA1, vB1)
        PROCESS(d0, vA0, vB0)
        PROCESS(d1, vA1, vB1)
    }
    {   // conn pair 2,3
        const int4 d2 = __ldg(&g_desc[co * CONN + 2]);
        const int4 d3 = __ldg(&g_desc[co * CONN + 3]);
        GATHER(d2, vA2, vB2)
        GATHER(d3, vA3, vB3)
        PROCESS(d2, vA2, vB2)
        PROCESS(d3, vA3, vB3)
    }
#undef GATHER
#undef PROCESS

    const float bs = __ldg(&bias[co]);
    const int ob = ((b * C_OUT + co) * HH) * WWW + hoAW + wo0;  // < 2^25: 32-bit ok
    float4 rA, rB;
    rA.x = aA0 + bs; rA.y = aA1 + bs; rA.z = aA2 + bs; rA.w = aA3 + bs;
    rB.x = aB0 + bs; rB.y = aB1 + bs; rB.z = aB2 + bs; rB.w = aB3 + bs;
    *reinterpret_cast<float4*>(out + ob)             = rA;
    *reinterpret_cast<float4*>(out + ob + 16 * WWW)  = rB;
}

extern "C" void kernel_launch(void* const* d_in, const int* in_sizes, int n_in,
                              void* d_out, int out_size)
{
    const float* x    = (const float*)d_in[0];
    const float* w    = (const float*)d_in[1];
    const float* bias = (const float*)d_in[2];
    const int*   conn = (const int*)  d_in[3];
    float*       out  = (float*)d_out;

    prep_kernel<<<2, 256>>>(w, conn);

    dim3 block(16, 16);                  // half-warp = contiguous 64-wo row
    dim3 grid(HH / 32, NB, C_OUT);       // (2, 32, 128); each thread: 2 rows
    lp_main<<<grid, block>>>(x, bias, out);
}